// round 11
// baseline (speedup 1.0000x reference)
#include <cuda_runtime.h>
#include <cuda_bf16.h>
#include <math.h>
#include <stdint.h>

#define FDIM 512
#define F4   128
#define NMAX 20608
#define EMAX 335872
#define TDK  0.1f
#define DT   0.2f
#define LNEPS 1e-5f

// ---------------- device scratch ----------------
__device__ float g_h0[(size_t)NMAX * FDIM];
__device__ float g_h1[(size_t)NMAX * FDIM];
__device__ float g_xr[(size_t)NMAX * FDIM];   // x @ Wr^T (precomputed)
__device__ uint4 g_ca[(size_t)NMAX * 128];    // split-bf16 h
__device__ uint4 g_cx[(size_t)NMAX * 128];    // split-bf16 x
__device__ uint4 g_cwt[512 * 128];            // split-bf16 Wt
__device__ uint4 g_cwr[512 * 128];            // split-bf16 Wr
__device__ float g_dinv[NMAX];
__device__ float g_ewself[NMAX];
__device__ int   g_cnt[NMAX];
__device__ int   g_cur[NMAX];
__device__ int   g_rp[NMAX + 1];
__device__ int2  g_edge[EMAX];
__device__ int   g_tmaxbits;   // ts > 0, monotonic, idempotent across replays

__device__ __forceinline__ float decode_scalar(const void* p) {
    int iv = *(const int*)p;
    float fv = __int_as_float(iv);
    float fa = fabsf(fv);
    if (isfinite(fv) && fa >= 1e-3f && fa <= 1e9f) return fv;
    return (float)iv;
}

// ---------------- prep ----------------
__global__ void k_prep(const float* __restrict__ ts, int e, int n, const void* gt) {
    int i = blockIdx.x * blockDim.x + threadIdx.x;
    if (i < n) { g_dinv[i] = 0.f; g_cnt[i] = 0; g_cur[i] = 0; }
    float m = -1.f;
    for (int k = i; k < e; k += gridDim.x * blockDim.x) m = fmaxf(m, ts[k]);
    if (i == 0) m = fmaxf(m, decode_scalar(gt));
    #pragma unroll
    for (int off = 16; off; off >>= 1)
        m = fmaxf(m, __shfl_xor_sync(0xffffffffu, m, off));
    if ((threadIdx.x & 31) == 0)
        atomicMax(&g_tmaxbits, __float_as_int(m));
}

__global__ void k_edge_deg(const int* __restrict__ ei, const float* __restrict__ ts, int e) {
    int i = blockIdx.x * blockDim.x + threadIdx.x;
    if (i >= e) return;
    float tmax = __int_as_float(g_tmaxbits);
    int dst = ei[e + i];
    float w = expf(-TDK * (tmax - ts[i]));
    atomicAdd(&g_dinv[dst], w);
    atomicAdd(&g_cnt[dst], 1);
}

__global__ void k_node(int n, const void* gt) {
    int v = blockIdx.x * blockDim.x + threadIdx.x;
    if (v >= n) return;
    float tmax = __int_as_float(g_tmaxbits);
    float ws = expf(-TDK * (tmax - decode_scalar(gt)));
    float d = g_dinv[v] + ws;
    float di = (d > 0.f) ? rsqrtf(d) : 0.f;
    g_dinv[v] = di;
    g_ewself[v] = di * di * ws;
}

// fast single-block scan: each thread owns a contiguous segment
__global__ void k_scan(int n) {
    __shared__ int wsum[32];
    int tid = threadIdx.x;
    int ch = (n + 1023) >> 10;
    int beg = tid * ch;
    int end = min(beg + ch, n);
    int s = 0;
    #pragma unroll 5
    for (int i = beg; i < end; i++) s += g_cnt[i];
    int lane = tid & 31, w = tid >> 5;
    int inc = s;
    #pragma unroll
    for (int o = 1; o < 32; o <<= 1) {
        int v = __shfl_up_sync(0xffffffffu, inc, o);
        if (lane >= o) inc += v;
    }
    if (lane == 31) wsum[w] = inc;
    __syncthreads();
    if (w == 0) {
        int v = wsum[lane];
        int wi = v;
        #pragma unroll
        for (int o = 1; o < 32; o <<= 1) {
            int u = __shfl_up_sync(0xffffffffu, wi, o);
            if (lane >= o) wi += u;
        }
        wsum[lane] = wi - v;
    }
    __syncthreads();
    int excl = wsum[w] + inc - s;
    int run = excl;
    #pragma unroll 5
    for (int i = beg; i < end; i++) {
        int c = g_cnt[i];
        g_rp[i] = run;
        run += c;
    }
    if (tid == 1023) g_rp[n] = excl + s;
}

__global__ void k_scatter(const int* __restrict__ ei, const float* __restrict__ ts, int e) {
    int i = blockIdx.x * blockDim.x + threadIdx.x;
    if (i >= e) return;
    float tmax = __int_as_float(g_tmaxbits);
    int src = ei[i];
    int dst = ei[e + i];
    float w = expf(-TDK * (tmax - ts[i]));
    int pos = g_rp[dst] + atomicAdd(&g_cur[dst], 1);
    g_edge[pos] = make_int2(src, __float_as_int(g_dinv[src] * w * g_dinv[dst]));
}

// ---------------- diffusion: one warp per node, 4-way LDG ILP ----------------
__global__ __launch_bounds__(256)
void k_diff(const float4* __restrict__ hin, float4* __restrict__ hout, int n) {
    __shared__ int2 se[8][32];
    int wid = threadIdx.x >> 5, lane = threadIdx.x & 31;
    int v = blockIdx.x * 8 + wid;
    if (v >= n) return;
    int b = g_rp[v], e2 = g_rp[v + 1];
    float4 a0 = make_float4(0.f, 0.f, 0.f, 0.f);
    float4 a1 = a0, a2 = a0, a3 = a0;
    for (int c = b; c < e2; c += 32) {
        int m = min(32, e2 - c);
        if (lane < m) se[wid][lane] = __ldg(&g_edge[c + lane]);
        __syncwarp();
        #pragma unroll 4
        for (int i = 0; i < m; i++) {
            int2 ed = se[wid][i];
            float w = __int_as_float(ed.y);
            const float4* hp = hin + (size_t)ed.x * F4 + lane;
            float4 v0 = __ldg(hp);
            float4 v1 = __ldg(hp + 32);
            float4 v2 = __ldg(hp + 64);
            float4 v3 = __ldg(hp + 96);
            a0.x = fmaf(w, v0.x, a0.x); a0.y = fmaf(w, v0.y, a0.y);
            a0.z = fmaf(w, v0.z, a0.z); a0.w = fmaf(w, v0.w, a0.w);
            a1.x = fmaf(w, v1.x, a1.x); a1.y = fmaf(w, v1.y, a1.y);
            a1.z = fmaf(w, v1.z, a1.z); a1.w = fmaf(w, v1.w, a1.w);
            a2.x = fmaf(w, v2.x, a2.x); a2.y = fmaf(w, v2.y, a2.y);
            a2.z = fmaf(w, v2.z, a2.z); a2.w = fmaf(w, v2.w, a2.w);
            a3.x = fmaf(w, v3.x, a3.x); a3.y = fmaf(w, v3.y, a3.y);
            a3.z = fmaf(w, v3.z, a3.z); a3.w = fmaf(w, v3.w, a3.w);
        }
        __syncwarp();
    }
    float cs = (1.f - DT) + DT * g_ewself[v];
    const float4* sp = hin + (size_t)v * F4 + lane;
    float4* op = hout + (size_t)v * F4 + lane;
    float4 s0 = __ldg(sp), s1 = __ldg(sp + 32), s2 = __ldg(sp + 64), s3 = __ldg(sp + 96);
    float4 o;
    o.x = cs * s0.x + DT * a0.x; o.y = cs * s0.y + DT * a0.y;
    o.z = cs * s0.z + DT * a0.z; o.w = cs * s0.w + DT * a0.w;
    op[0] = o;
    o.x = cs * s1.x + DT * a1.x; o.y = cs * s1.y + DT * a1.y;
    o.z = cs * s1.z + DT * a1.z; o.w = cs * s1.w + DT * a1.w;
    op[32] = o;
    o.x = cs * s2.x + DT * a2.x; o.y = cs * s2.y + DT * a2.y;
    o.z = cs * s2.z + DT * a2.z; o.w = cs * s2.w + DT * a2.w;
    op[64] = o;
    o.x = cs * s3.x + DT * a3.x; o.y = cs * s3.y + DT * a3.y;
    o.z = cs * s3.z + DT * a3.z; o.w = cs * s3.w + DT * a3.w;
    op[96] = o;
}

// ================= split-bf16 pre-conversion =================
__device__ __forceinline__ uint32_t bsplit2(float x, float y, uint32_t& t2) {
    __nv_bfloat16 hx = __float2bfloat16_rn(x);
    __nv_bfloat16 hy = __float2bfloat16_rn(y);
    float rx = x - __bfloat162float(hx);
    float ry = y - __bfloat162float(hy);
    __nv_bfloat16 lx = __float2bfloat16_rn(rx);
    __nv_bfloat16 ly = __float2bfloat16_rn(ry);
    t2 = (uint32_t)__bfloat16_as_ushort(lx) | ((uint32_t)__bfloat16_as_ushort(ly) << 16);
    return (uint32_t)__bfloat16_as_ushort(hx) | ((uint32_t)__bfloat16_as_ushort(hy) << 16);
}

__global__ void k_cvt(const float* __restrict__ in, uint4* __restrict__ out, int total) {
    int idx = blockIdx.x * blockDim.x + threadIdx.x;
    if (idx >= total) return;
    int row = idx >> 6;
    int rem = idx & 63;
    int kc = rem >> 1;
    int h = rem & 1;
    const float* p = in + (size_t)row * FDIM + kc * 16 + 4 * h;
    float4 v0 = *(const float4*)(p);
    float4 v1 = *(const float4*)(p + 8);
    uint32_t l0, l1, l4, l5;
    uint32_t h0 = bsplit2(v0.x, v0.y, l0);
    uint32_t h1 = bsplit2(v0.z, v0.w, l1);
    uint32_t h4 = bsplit2(v1.x, v1.y, l4);
    uint32_t h5 = bsplit2(v1.z, v1.w, l5);
    size_t ob = (size_t)row * 128 + kc * 4 + 2 * h;
    out[ob]     = make_uint4(h0, h4, l0, l4);
    out[ob + 1] = make_uint4(h1, h5, l1, l5);
}

// ================= mma.sync bf16 split SGEMM =================
#define NKC   32
#define SMEMB 49152
#define SB(s, mat, row, q) sbuf[((((s) * 2 + (mat)) * 128 + (row)) << 2) + (q)]

__device__ __forceinline__ uint32_t smem_u32(const void* p) {
    uint32_t a;
    asm("{ .reg .u64 t; cvta.to.shared.u64 t, %1; cvt.u32.u64 %0, t; }" : "=r"(a) : "l"(p));
    return a;
}
__device__ __forceinline__ void cp16(uint32_t d, const void* s) {
    asm volatile("cp.async.ca.shared.global [%0], [%1], 16;" :: "r"(d), "l"(s));
}
__device__ __forceinline__ void cp_commit() {
    asm volatile("cp.async.commit_group;" ::: "memory");
}
__device__ __forceinline__ void cp_wait1() {
    asm volatile("cp.async.wait_group 1;" ::: "memory");
}
__device__ __forceinline__ void cp_wait0() {
    asm volatile("cp.async.wait_group 0;" ::: "memory");
}

__device__ __forceinline__ void mma_bf16(float* d, const uint32_t* a, const uint32_t* b) {
    asm volatile(
        "mma.sync.aligned.m16n8k16.row.col.f32.bf16.bf16.f32 "
        "{%0,%1,%2,%3}, {%4,%5,%6,%7}, {%8,%9}, {%0,%1,%2,%3};"
        : "+f"(d[0]), "+f"(d[1]), "+f"(d[2]), "+f"(d[3])
        : "r"(a[0]), "r"(a[1]), "r"(a[2]), "r"(a[3]), "r"(b[0]), "r"(b[1]));
}

// MODE 2: C = A*B^T                       (plain)
// MODE 3: C = relu(A*B^T + bias[n]) + R[m][n]
template <int MODE>
__global__ __launch_bounds__(256, 1)
void k_gemm_mma(const uint4* __restrict__ A4, const uint4* __restrict__ B4,
                const float* __restrict__ bias, const float* __restrict__ R,
                float* __restrict__ C, int M) {
    extern __shared__ uint4 sbuf[];
    int tid = threadIdx.x;
    int lane = tid & 31, wid = tid >> 5;
    int warpM = wid >> 2;
    int warpN = wid & 3;
    int g = lane >> 2, t = lane & 3;
    int m0 = blockIdx.y * 128;
    int n0 = blockIdx.x * 128;

    int lr = tid >> 1;
    int h = tid & 1;
    const uint4* Ag = A4 + (size_t)(m0 + lr) * 128 + 2 * h;
    const uint4* Bg = B4 + (size_t)(n0 + lr) * 128 + 2 * h;

    float acc[4][4][4];
    #pragma unroll
    for (int i = 0; i < 4; i++)
        #pragma unroll
        for (int j = 0; j < 4; j++)
            #pragma unroll
            for (int k = 0; k < 4; k++) acc[i][j][k] = 0.f;

    #pragma unroll
    for (int p = 0; p < 2; p++) {
        uint32_t da = smem_u32(&SB(p, 0, lr, 2 * h));
        uint32_t db = smem_u32(&SB(p, 1, lr, 2 * h));
        cp16(da, Ag + p * 4);      cp16(da + 16, Ag + p * 4 + 1);
        cp16(db, Bg + p * 4);      cp16(db + 16, Bg + p * 4 + 1);
        cp_commit();
    }

    int arow = warpM * 64 + g;
    int bn = warpN * 32 + g;

    for (int kc = 0; kc < NKC; kc++) {
        if (kc >= NKC - 2) cp_wait0(); else cp_wait1();
        __syncthreads();

        if (kc + 2 < NKC) {
            int ps = (kc + 2) % 3;
            uint32_t da = smem_u32(&SB(ps, 0, lr, 2 * h));
            uint32_t db = smem_u32(&SB(ps, 1, lr, 2 * h));
            cp16(da, Ag + (kc + 2) * 4);  cp16(da + 16, Ag + (kc + 2) * 4 + 1);
            cp16(db, Bg + (kc + 2) * 4);  cp16(db + 16, Bg + (kc + 2) * 4 + 1);
            cp_commit();
        }

        int s = kc % 3;
        uint32_t a1[4][4], a2[4][4], b1[4][2], b2[4][2];
        #pragma unroll
        for (int mt = 0; mt < 4; mt++) {
            uint4 va  = SB(s, 0, arow + mt * 16, t);
            uint4 va8 = SB(s, 0, arow + mt * 16 + 8, t);
            a1[mt][0] = va.x; a1[mt][1] = va8.x; a1[mt][2] = va.y; a1[mt][3] = va8.y;
            a2[mt][0] = va.z; a2[mt][1] = va8.z; a2[mt][2] = va.w; a2[mt][3] = va8.w;
        }
        #pragma unroll
        for (int nt = 0; nt < 4; nt++) {
            uint4 vb = SB(s, 1, bn + nt * 8, t);
            b1[nt][0] = vb.x; b1[nt][1] = vb.y;
            b2[nt][0] = vb.z; b2[nt][1] = vb.w;
        }
        #pragma unroll
        for (int mt = 0; mt < 4; mt++)
            #pragma unroll
            for (int nt = 0; nt < 4; nt++) {
                mma_bf16(acc[mt][nt], a1[mt], b1[nt]);
                mma_bf16(acc[mt][nt], a1[mt], b2[nt]);
                mma_bf16(acc[mt][nt], a2[mt], b1[nt]);
            }
    }

    #pragma unroll
    for (int mt = 0; mt < 4; mt++) {
        int row0 = m0 + warpM * 64 + mt * 16 + g;
        #pragma unroll
        for (int half = 0; half < 2; half++) {
            int row = row0 + half * 8;
            if (row >= M) continue;
            #pragma unroll
            for (int nt = 0; nt < 4; nt++) {
                int col = n0 + warpN * 32 + nt * 8 + t * 2;
                float v0 = acc[mt][nt][half * 2 + 0];
                float v1 = acc[mt][nt][half * 2 + 1];
                if (MODE == 3) {
                    float2 bb = *(const float2*)&bias[col];
                    float2 rr = *(const float2*)&R[(size_t)row * FDIM + col];
                    v0 = fmaxf(v0 + bb.x, 0.f) + rr.x;
                    v1 = fmaxf(v1 + bb.y, 0.f) + rr.y;
                }
                *(float2*)&C[(size_t)row * FDIM + col] = make_float2(v0, v1);
            }
        }
    }
}

// ---------------- layernorm ----------------
__global__ void k_ln(float* __restrict__ io, const float* __restrict__ gamma,
                     const float* __restrict__ beta) {
    int r = blockIdx.x;
    int t = threadIdx.x;
    float4* row = ((float4*)io) + (size_t)r * F4;
    float4 v = row[t];
    float s = v.x + v.y + v.z + v.w;
    float q = v.x * v.x + v.y * v.y + v.z * v.z + v.w * v.w;
    #pragma unroll
    for (int off = 16; off; off >>= 1) {
        s += __shfl_xor_sync(0xffffffffu, s, off);
        q += __shfl_xor_sync(0xffffffffu, q, off);
    }
    __shared__ float ss[4], sq[4];
    if ((t & 31) == 0) { ss[t >> 5] = s; sq[t >> 5] = q; }
    __syncthreads();
    s = ss[0] + ss[1] + ss[2] + ss[3];
    q = sq[0] + sq[1] + sq[2] + sq[3];
    float mu = s * (1.f / FDIM);
    float var = q * (1.f / FDIM) - mu * mu;
    float inv = rsqrtf(var + LNEPS);
    float4 g = ((const float4*)gamma)[t];
    float4 bb = ((const float4*)beta)[t];
    v.x = (v.x - mu) * inv * g.x + bb.x;
    v.y = (v.y - mu) * inv * g.y + bb.y;
    v.z = (v.z - mu) * inv * g.z + bb.z;
    v.w = (v.w - mu) * inv * g.w + bb.w;
    row[t] = v;
}

// ---------------- launch ----------------
extern "C" void kernel_launch(void* const* d_in, const int* in_sizes, int n_in,
                              void* d_out, int out_size) {
    const float* x     = (const float*)d_in[0];
    const int*   ei    = (const int*)d_in[1];
    const float* ts    = (const float*)d_in[2];
    const float* Wt    = (const float*)d_in[3];
    const float* bt    = (const float*)d_in[4];
    const float* Wr    = (const float*)d_in[5];
    const float* gamma = (const float*)d_in[6];
    const float* beta  = (const float*)d_in[7];
    const void*  gt    = d_in[8];

    int n = in_sizes[0] / FDIM;
    int e = in_sizes[1] / 2;

    float *h0, *h1, *xr;
    uint4 *ca, *cx, *cwt, *cwr;
    cudaGetSymbolAddress((void**)&h0, g_h0);
    cudaGetSymbolAddress((void**)&h1, g_h1);
    cudaGetSymbolAddress((void**)&xr, g_xr);
    cudaGetSymbolAddress((void**)&ca, g_ca);
    cudaGetSymbolAddress((void**)&cx, g_cx);
    cudaGetSymbolAddress((void**)&cwt, g_cwt);
    cudaGetSymbolAddress((void**)&cwr, g_cwr);

    cudaFuncSetAttribute(k_gemm_mma<2>, cudaFuncAttributeMaxDynamicSharedMemorySize, SMEMB);
    cudaFuncSetAttribute(k_gemm_mma<3>, cudaFuncAttributeMaxDynamicSharedMemorySize, SMEMB);

    const int tb = 256;
    dim3 gg(FDIM / 128, (n + 127) / 128);   // (4, 157)

    // launches 0-2; launch 3 (profiled by ncu -s 5 -c 1) = plain GEMM
    k_cvt<<<(512 * 64 + tb - 1) / tb, tb>>>(Wr, cwr, 512 * 64);
    k_cvt<<<(n * 64 + tb - 1) / tb, tb>>>(x, cx, n * 64);
    k_prep<<<(n + tb - 1) / tb, tb>>>(ts, e, n, gt);
    k_gemm_mma<2><<<gg, 256, SMEMB>>>(cx, cwr, nullptr, nullptr, xr, n);  // xr = x@Wr^T

    k_edge_deg<<<(e + tb - 1) / tb, tb>>>(ei, ts, e);
    k_node<<<(n + tb - 1) / tb, tb>>>(n, gt);
    k_scan<<<1, 1024>>>(n);
    k_scatter<<<(e + tb - 1) / tb, tb>>>(ei, ts, e);
    k_cvt<<<(512 * 64 + tb - 1) / tb, tb>>>(Wt, cwt, 512 * 64);

    // 5 Euler diffusion steps (warp-per-node); result in h1
    int gb = (n + 7) / 8;
    k_diff<<<gb, 256>>>((const float4*)x,  (float4*)h1, n);
    k_diff<<<gb, 256>>>((const float4*)h1, (float4*)h0, n);
    k_diff<<<gb, 256>>>((const float4*)h0, (float4*)h1, n);
    k_diff<<<gb, 256>>>((const float4*)h1, (float4*)h0, n);
    k_diff<<<gb, 256>>>((const float4*)h0, (float4*)h1, n);

    // convert diffused h to split-bf16
    k_cvt<<<(n * 64 + tb - 1) / tb, tb>>>(h1, ca, n * 64);

    float* out = (float*)d_out;
    k_gemm_mma<3><<<gg, 256, SMEMB>>>(ca, cwt, bt, xr, out, n);  // out = relu(h@Wt^T+b) + xr
    k_ln<<<n, 128>>>(out, gamma, beta);
}

// round 14
// speedup vs baseline: 1.0227x; 1.0227x over previous
#include <cuda_runtime.h>
#include <cuda_bf16.h>
#include <cuda_fp16.h>
#include <math.h>
#include <stdint.h>

#define FDIM 512
#define F4   128
#define NMAX 20608
#define EMAX 335872
#define TDK  0.1f
#define DT   0.2f
#define LNEPS 1e-5f

// ---------------- device scratch ----------------
__device__ float g_h0[(size_t)NMAX * FDIM];
__device__ float g_h1[(size_t)NMAX * FDIM];
__device__ float g_xr[(size_t)NMAX * FDIM];   // x @ Wr^T (precomputed)
__device__ uint2 g_hfA[(size_t)NMAX * 128];   // fp16 shadow (512 halves/row)
__device__ uint2 g_hfB[(size_t)NMAX * 128];
__device__ uint4 g_ca[(size_t)NMAX * 128];    // split-bf16 h
__device__ uint4 g_cx[(size_t)NMAX * 128];    // split-bf16 x
__device__ uint4 g_cwt[512 * 128];            // split-bf16 Wt
__device__ uint4 g_cwr[512 * 128];            // split-bf16 Wr
__device__ float g_dinv[NMAX];
__device__ float g_ewself[NMAX];
__device__ int   g_cnt[NMAX];
__device__ int   g_cur[NMAX];
__device__ int   g_rp[NMAX + 1];
__device__ int2  g_edge[EMAX];
__device__ int   g_tmaxbits;   // ts > 0, monotonic, idempotent across replays

__device__ __forceinline__ float decode_scalar(const void* p) {
    int iv = *(const int*)p;
    float fv = __int_as_float(iv);
    float fa = fabsf(fv);
    if (isfinite(fv) && fa >= 1e-3f && fa <= 1e9f) return fv;
    return (float)iv;
}

// ---------------- prep ----------------
__global__ void k_prep(const float* __restrict__ ts, int e, int n, const void* gt) {
    int i = blockIdx.x * blockDim.x + threadIdx.x;
    if (i < n) { g_dinv[i] = 0.f; g_cnt[i] = 0; g_cur[i] = 0; }
    float m = -1.f;
    for (int k = i; k < e; k += gridDim.x * blockDim.x) m = fmaxf(m, ts[k]);
    if (i == 0) m = fmaxf(m, decode_scalar(gt));
    #pragma unroll
    for (int off = 16; off; off >>= 1)
        m = fmaxf(m, __shfl_xor_sync(0xffffffffu, m, off));
    if ((threadIdx.x & 31) == 0)
        atomicMax(&g_tmaxbits, __float_as_int(m));
}

__global__ void k_edge_deg(const int* __restrict__ ei, const float* __restrict__ ts, int e) {
    int i = blockIdx.x * blockDim.x + threadIdx.x;
    if (i >= e) return;
    float tmax = __int_as_float(g_tmaxbits);
    int dst = ei[e + i];
    float w = expf(-TDK * (tmax - ts[i]));
    atomicAdd(&g_dinv[dst], w);
    atomicAdd(&g_cnt[dst], 1);
}

// scan + node-finalize fused: single block, each thread owns a contiguous segment
__global__ void k_scan(int n, const void* gt) {
    __shared__ int wsum[32];
    int tid = threadIdx.x;
    int ch = (n + 1023) >> 10;
    int beg = tid * ch;
    int end = min(beg + ch, n);
    float tmax = __int_as_float(g_tmaxbits);
    float ws = expf(-TDK * (tmax - decode_scalar(gt)));
    int s = 0;
    #pragma unroll 5
    for (int i = beg; i < end; i++) {
        // node finalize (deg -> dinv, self weight)
        float d = g_dinv[i] + ws;
        float di = (d > 0.f) ? rsqrtf(d) : 0.f;
        g_dinv[i] = di;
        g_ewself[i] = di * di * ws;
        s += g_cnt[i];
    }
    int lane = tid & 31, w = tid >> 5;
    int inc = s;
    #pragma unroll
    for (int o = 1; o < 32; o <<= 1) {
        int v = __shfl_up_sync(0xffffffffu, inc, o);
        if (lane >= o) inc += v;
    }
    if (lane == 31) wsum[w] = inc;
    __syncthreads();
    if (w == 0) {
        int v = wsum[lane];
        int wi = v;
        #pragma unroll
        for (int o = 1; o < 32; o <<= 1) {
            int u = __shfl_up_sync(0xffffffffu, wi, o);
            if (lane >= o) wi += u;
        }
        wsum[lane] = wi - v;
    }
    __syncthreads();
    int excl = wsum[w] + inc - s;
    int run = excl;
    #pragma unroll 5
    for (int i = beg; i < end; i++) {
        int c = g_cnt[i];
        g_rp[i] = run;
        run += c;
    }
    if (tid == 1023) g_rp[n] = excl + s;
}

__global__ void k_scatter(const int* __restrict__ ei, const float* __restrict__ ts, int e) {
    int i = blockIdx.x * blockDim.x + threadIdx.x;
    if (i >= e) return;
    float tmax = __int_as_float(g_tmaxbits);
    int src = ei[i];
    int dst = ei[e + i];
    float w = expf(-TDK * (tmax - ts[i]));
    int pos = g_rp[dst] + atomicAdd(&g_cur[dst], 1);
    g_edge[pos] = make_int2(src, __float_as_int(g_dinv[src] * w * g_dinv[dst]));
}

// ---------------- fp16 shadow of a fp32 matrix ----------------
__global__ void k_f32to16(const float4* __restrict__ in, uint2* __restrict__ out) {
    size_t i = (size_t)blockIdx.x * 128 + threadIdx.x;
    float4 v = in[i];
    __half2 p0 = __floats2half2_rn(v.x, v.y);
    __half2 p1 = __floats2half2_rn(v.z, v.w);
    out[i] = make_uint2(*(uint32_t*)&p0, *(uint32_t*)&p1);
}

// ------- diffusion: warp-per-node, fp16 gather (4-way ILP), fp32 state -------
template <int WRITE16>
__global__ __launch_bounds__(256)
void k_diff(const float4* __restrict__ hin, const uint2* __restrict__ hfin,
            float4* __restrict__ hout, uint2* __restrict__ hfout, int n) {
    __shared__ int2 se[8][32];
    int wid = threadIdx.x >> 5, lane = threadIdx.x & 31;
    int v = blockIdx.x * 8 + wid;
    if (v >= n) return;
    int b = g_rp[v], e2 = g_rp[v + 1];
    float4 a0 = make_float4(0.f, 0.f, 0.f, 0.f);
    float4 a1 = a0, a2 = a0, a3 = a0;
    for (int c = b; c < e2; c += 32) {
        int m = min(32, e2 - c);
        if (lane < m) se[wid][lane] = __ldg(&g_edge[c + lane]);
        __syncwarp();
        #pragma unroll 4
        for (int i = 0; i < m; i++) {
            int2 ed = se[wid][i];
            float w = __int_as_float(ed.y);
            const uint2* hp = hfin + (size_t)ed.x * 128 + lane;
            uint2 q0 = __ldg(hp);
            uint2 q1 = __ldg(hp + 32);
            uint2 q2 = __ldg(hp + 64);
            uint2 q3 = __ldg(hp + 96);
            float2 f;
            f = __half22float2(*(__half2*)&q0.x);
            a0.x = fmaf(w, f.x, a0.x); a0.y = fmaf(w, f.y, a0.y);
            f = __half22float2(*(__half2*)&q0.y);
            a0.z = fmaf(w, f.x, a0.z); a0.w = fmaf(w, f.y, a0.w);
            f = __half22float2(*(__half2*)&q1.x);
            a1.x = fmaf(w, f.x, a1.x); a1.y = fmaf(w, f.y, a1.y);
            f = __half22float2(*(__half2*)&q1.y);
            a1.z = fmaf(w, f.x, a1.z); a1.w = fmaf(w, f.y, a1.w);
            f = __half22float2(*(__half2*)&q2.x);
            a2.x = fmaf(w, f.x, a2.x); a2.y = fmaf(w, f.y, a2.y);
            f = __half22float2(*(__half2*)&q2.y);
            a2.z = fmaf(w, f.x, a2.z); a2.w = fmaf(w, f.y, a2.w);
            f = __half22float2(*(__half2*)&q3.x);
            a3.x = fmaf(w, f.x, a3.x); a3.y = fmaf(w, f.y, a3.y);
            f = __half22float2(*(__half2*)&q3.y);
            a3.z = fmaf(w, f.x, a3.z); a3.w = fmaf(w, f.y, a3.w);
        }
        __syncwarp();
    }
    float cs = (1.f - DT) + DT * g_ewself[v];
    const float4* sp = hin + (size_t)v * F4 + lane;
    float4* op = hout + (size_t)v * F4 + lane;
    uint2* fp = hfout + (size_t)v * 128 + lane;
    float4 s0 = __ldg(sp), s1 = __ldg(sp + 32), s2 = __ldg(sp + 64), s3 = __ldg(sp + 96);
    float4 o;
    o.x = cs * s0.x + DT * a0.x; o.y = cs * s0.y + DT * a0.y;
    o.z = cs * s0.z + DT * a0.z; o.w = cs * s0.w + DT * a0.w;
    op[0] = o;
    if (WRITE16) {
        __half2 p0 = __floats2half2_rn(o.x, o.y), p1 = __floats2half2_rn(o.z, o.w);
        fp[0] = make_uint2(*(uint32_t*)&p0, *(uint32_t*)&p1);
    }
    o.x = cs * s1.x + DT * a1.x; o.y = cs * s1.y + DT * a1.y;
    o.z = cs * s1.z + DT * a1.z; o.w = cs * s1.w + DT * a1.w;
    op[32] = o;
    if (WRITE16) {
        __half2 p0 = __floats2half2_rn(o.x, o.y), p1 = __floats2half2_rn(o.z, o.w);
        fp[32] = make_uint2(*(uint32_t*)&p0, *(uint32_t*)&p1);
    }
    o.x = cs * s2.x + DT * a2.x; o.y = cs * s2.y + DT * a2.y;
    o.z = cs * s2.z + DT * a2.z; o.w = cs * s2.w + DT * a2.w;
    op[64] = o;
    if (WRITE16) {
        __half2 p0 = __floats2half2_rn(o.x, o.y), p1 = __floats2half2_rn(o.z, o.w);
        fp[64] = make_uint2(*(uint32_t*)&p0, *(uint32_t*)&p1);
    }
    o.x = cs * s3.x + DT * a3.x; o.y = cs * s3.y + DT * a3.y;
    o.z = cs * s3.z + DT * a3.z; o.w = cs * s3.w + DT * a3.w;
    op[96] = o;
    if (WRITE16) {
        __half2 p0 = __floats2half2_rn(o.x, o.y), p1 = __floats2half2_rn(o.z, o.w);
        fp[96] = make_uint2(*(uint32_t*)&p0, *(uint32_t*)&p1);
    }
}

// ================= split-bf16 pre-conversion =================
__device__ __forceinline__ uint32_t bsplit2(float x, float y, uint32_t& t2) {
    __nv_bfloat16 hx = __float2bfloat16_rn(x);
    __nv_bfloat16 hy = __float2bfloat16_rn(y);
    float rx = x - __bfloat162float(hx);
    float ry = y - __bfloat162float(hy);
    __nv_bfloat16 lx = __float2bfloat16_rn(rx);
    __nv_bfloat16 ly = __float2bfloat16_rn(ry);
    t2 = (uint32_t)__bfloat16_as_ushort(lx) | ((uint32_t)__bfloat16_as_ushort(ly) << 16);
    return (uint32_t)__bfloat16_as_ushort(hx) | ((uint32_t)__bfloat16_as_ushort(hy) << 16);
}

__device__ __forceinline__ void cvt_one(const float* __restrict__ in,
                                        uint4* __restrict__ out, int idx) {
    int row = idx >> 6;
    int rem = idx & 63;
    int kc = rem >> 1;
    int h = rem & 1;
    const float* p = in + (size_t)row * FDIM + kc * 16 + 4 * h;
    float4 v0 = *(const float4*)(p);
    float4 v1 = *(const float4*)(p + 8);
    uint32_t l0, l1, l4, l5;
    uint32_t h0 = bsplit2(v0.x, v0.y, l0);
    uint32_t h1 = bsplit2(v0.z, v0.w, l1);
    uint32_t h4 = bsplit2(v1.x, v1.y, l4);
    uint32_t h5 = bsplit2(v1.z, v1.w, l5);
    size_t ob = (size_t)row * 128 + kc * 4 + 2 * h;
    out[ob]     = make_uint4(h0, h4, l0, l4);
    out[ob + 1] = make_uint4(h1, h5, l1, l5);
}

__global__ void k_cvt(const float* __restrict__ in, uint4* __restrict__ out, int total) {
    int idx = blockIdx.x * blockDim.x + threadIdx.x;
    if (idx >= total) return;
    cvt_one(in, out, idx);
}

// both weight matrices in one kernel
__global__ void k_cvtw(const float* __restrict__ Wt, const float* __restrict__ Wr,
                       uint4* __restrict__ cwt, uint4* __restrict__ cwr) {
    int idx = blockIdx.x * blockDim.x + threadIdx.x;
    const int half = 512 * 64;
    if (idx < half) cvt_one(Wt, cwt, idx);
    else if (idx < 2 * half) cvt_one(Wr, cwr, idx - half);
}

// ================= mma.sync bf16 split SGEMM =================
// KCH=32 per pipeline stage (2 sub-chunks of 16); 3-stage cp.async ring.
#define NSTG  16
#define SMEMB 98304
#define SB2(s, mat, c, row, q) \
    sbuf[((((((s) * 2 + (mat)) * 2 + (c)) * 128 + (row))) << 2) + (q)]

__device__ __forceinline__ uint32_t smem_u32(const void* p) {
    uint32_t a;
    asm("{ .reg .u64 t; cvta.to.shared.u64 t, %1; cvt.u32.u64 %0, t; }" : "=r"(a) : "l"(p));
    return a;
}
__device__ __forceinline__ void cp16(uint32_t d, const void* s) {
    asm volatile("cp.async.ca.shared.global [%0], [%1], 16;" :: "r"(d), "l"(s));
}
__device__ __forceinline__ void cp_commit() {
    asm volatile("cp.async.commit_group;" ::: "memory");
}
__device__ __forceinline__ void cp_wait1() {
    asm volatile("cp.async.wait_group 1;" ::: "memory");
}
__device__ __forceinline__ void cp_wait0() {
    asm volatile("cp.async.wait_group 0;" ::: "memory");
}

__device__ __forceinline__ void mma_bf16(float* d, const uint32_t* a, const uint32_t* b) {
    asm volatile(
        "mma.sync.aligned.m16n8k16.row.col.f32.bf16.bf16.f32 "
        "{%0,%1,%2,%3}, {%4,%5,%6,%7}, {%8,%9}, {%0,%1,%2,%3};"
        : "+f"(d[0]), "+f"(d[1]), "+f"(d[2]), "+f"(d[3])
        : "r"(a[0]), "r"(a[1]), "r"(a[2]), "r"(a[3]), "r"(b[0]), "r"(b[1]));
}

// MODE 2: C = A*B^T ;  MODE 3: C = relu(A*B^T + bias[n]) + R[m][n]
template <int MODE>
__global__ __launch_bounds__(256, 1)
void k_gemm_mma(const uint4* __restrict__ A4, const uint4* __restrict__ B4,
                const float* __restrict__ bias, const float* __restrict__ R,
                float* __restrict__ C, int M) {
    extern __shared__ uint4 sbuf[];
    int tid = threadIdx.x;
    int lane = tid & 31, wid = tid >> 5;
    int warpM = wid >> 2;
    int warpN = wid & 3;
    int g = lane >> 2, t = lane & 3;
    int m0 = blockIdx.y * 128;
    int n0 = blockIdx.x * 128;

    int lr = tid >> 1;
    int h = tid & 1;
    const uint4* Ag = A4 + (size_t)(m0 + lr) * 128 + 2 * h;
    const uint4* Bg = B4 + (size_t)(n0 + lr) * 128 + 2 * h;

    float acc[4][4][4];
    #pragma unroll
    for (int i = 0; i < 4; i++)
        #pragma unroll
        for (int j = 0; j < 4; j++)
            #pragma unroll
            for (int k = 0; k < 4; k++) acc[i][j][k] = 0.f;

    // prologue: stages 0,1 (chunks 0..3)
    #pragma unroll
    for (int p = 0; p < 2; p++) {
        #pragma unroll
        for (int c = 0; c < 2; c++) {
            int kc = p * 2 + c;
            uint32_t da = smem_u32(&SB2(p, 0, c, lr, 2 * h));
            uint32_t db = smem_u32(&SB2(p, 1, c, lr, 2 * h));
            cp16(da, Ag + kc * 4);      cp16(da + 16, Ag + kc * 4 + 1);
            cp16(db, Bg + kc * 4);      cp16(db + 16, Bg + kc * 4 + 1);
        }
        cp_commit();
    }

    int arow = warpM * 64 + g;
    int bn = warpN * 32 + g;

    for (int st = 0; st < NSTG; st++) {
        if (st >= NSTG - 2) cp_wait0(); else cp_wait1();
        __syncthreads();

        if (st + 2 < NSTG) {
            int ps = (st + 2) % 3;
            #pragma unroll
            for (int c = 0; c < 2; c++) {
                int kc = (st + 2) * 2 + c;
                uint32_t da = smem_u32(&SB2(ps, 0, c, lr, 2 * h));
                uint32_t db = smem_u32(&SB2(ps, 1, c, lr, 2 * h));
                cp16(da, Ag + kc * 4);  cp16(da + 16, Ag + kc * 4 + 1);
                cp16(db, Bg + kc * 4);  cp16(db + 16, Bg + kc * 4 + 1);
            }
            cp_commit();
        }

        int s = st % 3;
        #pragma unroll
        for (int c = 0; c < 2; c++) {
            uint32_t a1[4][4], a2[4][4], b1[4][2], b2[4][2];
            #pragma unroll
            for (int mt = 0; mt < 4; mt++) {
                uint4 va  = SB2(s, 0, c, arow + mt * 16, t);
                uint4 va8 = SB2(s, 0, c, arow + mt * 16 + 8, t);
                a1[mt][0] = va.x; a1[mt][1] = va8.x; a1[mt][2] = va.y; a1[mt][3] = va8.y;
                a2[mt][0] = va.z; a2[mt][1] = va8.z; a2[mt][2] = va.w; a2[mt][3] = va8.w;
            }
            #pragma unroll
            for (int nt = 0; nt < 4; nt++) {
                uint4 vb = SB2(s, 1, c, bn + nt * 8, t);
                b1[nt][0] = vb.x; b1[nt][1] = vb.y;
                b2[nt][0] = vb.z; b2[nt][1] = vb.w;
            }
            #pragma unroll
            for (int mt = 0; mt < 4; mt++)
                #pragma unroll
                for (int nt = 0; nt < 4; nt++) {
                    mma_bf16(acc[mt][nt], a1[mt], b1[nt]);
                    mma_bf16(acc[mt][nt], a1[mt], b2[nt]);
                    mma_bf16(acc[mt][nt], a2[mt], b1[nt]);
                }
        }
    }

    #pragma unroll
    for (int mt = 0; mt < 4; mt++) {
        int row0 = m0 + warpM * 64 + mt * 16 + g;
        #pragma unroll
        for (int half = 0; half < 2; half++) {
            int row = row0 + half * 8;
            if (row >= M) continue;
            #pragma unroll
            for (int nt = 0; nt < 4; nt++) {
                int col = n0 + warpN * 32 + nt * 8 + t * 2;
                float v0 = acc[mt][nt][half * 2 + 0];
                float v1 = acc[mt][nt][half * 2 + 1];
                if (MODE == 3) {
                    float2 bb = *(const float2*)&bias[col];
                    float2 rr = *(const float2*)&R[(size_t)row * FDIM + col];
                    v0 = fmaxf(v0 + bb.x, 0.f) + rr.x;
                    v1 = fmaxf(v1 + bb.y, 0.f) + rr.y;
                }
                *(float2*)&C[(size_t)row * FDIM + col] = make_float2(v0, v1);
            }
        }
    }
}

// ---------------- layernorm ----------------
__global__ void k_ln(float* __restrict__ io, const float* __restrict__ gamma,
                     const float* __restrict__ beta) {
    int r = blockIdx.x;
    int t = threadIdx.x;
    float4* row = ((float4*)io) + (size_t)r * F4;
    float4 v = row[t];
    float s = v.x + v.y + v.z + v.w;
    float q = v.x * v.x + v.y * v.y + v.z * v.z + v.w * v.w;
    #pragma unroll
    for (int off = 16; off; off >>= 1) {
        s += __shfl_xor_sync(0xffffffffu, s, off);
        q += __shfl_xor_sync(0xffffffffu, q, off);
    }
    __shared__ float ss[4], sq[4];
    if ((t & 31) == 0) { ss[t >> 5] = s; sq[t >> 5] = q; }
    __syncthreads();
    s = ss[0] + ss[1] + ss[2] + ss[3];
    q = sq[0] + sq[1] + sq[2] + sq[3];
    float mu = s * (1.f / FDIM);
    float var = q * (1.f / FDIM) - mu * mu;
    float inv = rsqrtf(var + LNEPS);
    float4 g = ((const float4*)gamma)[t];
    float4 bb = ((const float4*)beta)[t];
    v.x = (v.x - mu) * inv * g.x + bb.x;
    v.y = (v.y - mu) * inv * g.y + bb.y;
    v.z = (v.z - mu) * inv * g.z + bb.z;
    v.w = (v.w - mu) * inv * g.w + bb.w;
    row[t] = v;
}

// ---------------- launch ----------------
extern "C" void kernel_launch(void* const* d_in, const int* in_sizes, int n_in,
                              void* d_out, int out_size) {
    const float* x     = (const float*)d_in[0];
    const int*   ei    = (const int*)d_in[1];
    const float* ts    = (const float*)d_in[2];
    const float* Wt    = (const float*)d_in[3];
    const float* bt    = (const float*)d_in[4];
    const float* Wr    = (const float*)d_in[5];
    const float* gamma = (const float*)d_in[6];
    const float* beta  = (const float*)d_in[7];
    const void*  gt    = d_in[8];

    int n = in_sizes[0] / FDIM;
    int e = in_sizes[1] / 2;

    float *h0, *h1, *xr;
    uint2 *hfA, *hfB;
    uint4 *ca, *cx, *cwt, *cwr;
    cudaGetSymbolAddress((void**)&h0, g_h0);
    cudaGetSymbolAddress((void**)&h1, g_h1);
    cudaGetSymbolAddress((void**)&xr, g_xr);
    cudaGetSymbolAddress((void**)&hfA, g_hfA);
    cudaGetSymbolAddress((void**)&hfB, g_hfB);
    cudaGetSymbolAddress((void**)&ca, g_ca);
    cudaGetSymbolAddress((void**)&cx, g_cx);
    cudaGetSymbolAddress((void**)&cwt, g_cwt);
    cudaGetSymbolAddress((void**)&cwr, g_cwr);

    cudaFuncSetAttribute(k_gemm_mma<2>, cudaFuncAttributeMaxDynamicSharedMemorySize, SMEMB);
    cudaFuncSetAttribute(k_gemm_mma<3>, cudaFuncAttributeMaxDynamicSharedMemorySize, SMEMB);

    const int tb = 256;
    dim3 gg(FDIM / 128, (n + 127) / 128);   // (4, 157)

    // launch index 3 = plain GEMM (profiled by ncu)
    k_cvtw<<<(2 * 512 * 64 + tb - 1) / tb, tb>>>(Wt, Wr, cwt, cwr);
    k_cvt<<<(n * 64 + tb - 1) / tb, tb>>>(x, cx, n * 64);
    k_prep<<<(n + tb - 1) / tb, tb>>>(ts, e, n, gt);
    k_gemm_mma<2><<<gg, 256, SMEMB>>>(cx, cwr, nullptr, nullptr, xr, n);  // xr = x@Wr^T

    k_edge_deg<<<(e + tb - 1) / tb, tb>>>(ei, ts, e);
    k_scan<<<1, 1024>>>(n, gt);
    k_scatter<<<(e + tb - 1) / tb, tb>>>(ei, ts, e);
    k_f32to16<<<n, 128>>>((const float4*)x, hfA);

    // 5 Euler diffusion steps (warp-per-node, fp16 gather); result in h1
    int gb = (n + 7) / 8;
    k_diff<1><<<gb, 256>>>((const float4*)x,  hfA, (float4*)h1, hfB, n);
    k_diff<1><<<gb, 256>>>((const float4*)h1, hfB, (float4*)h0, hfA, n);
    k_diff<1><<<gb, 256>>>((const float4*)h0, hfA, (float4*)h1, hfB, n);
    k_diff<1><<<gb, 256>>>((const float4*)h1, hfB, (float4*)h0, hfA, n);
    k_diff<0><<<gb, 256>>>((const float4*)h0, hfA, (float4*)h1, hfB, n);

    // convert diffused h to split-bf16
    k_cvt<<<(n * 64 + tb - 1) / tb, tb>>>(h1, ca, n * 64);

    float* out = (float*)d_out;
    k_gemm_mma<3><<<gg, 256, SMEMB>>>(ca, cwt, bt, xr, out, n);  // out = relu(h@Wt^T+b)+xr
    k_ln<<<n, 128>>>(out, gamma, beta);
}

// round 16
// speedup vs baseline: 1.0423x; 1.0192x over previous
#include <cuda_runtime.h>
#include <cuda_bf16.h>
#include <cuda_fp16.h>
#include <math.h>
#include <stdint.h>

#define FDIM 512
#define F4   128
#define NMAX 20608
#define EMAX 335872
#define TDK  0.1f
#define DT   0.2f
#define LNEPS 1e-5f

// ---------------- device scratch ----------------
__device__ float g_h0[(size_t)NMAX * FDIM];
__device__ float g_h1[(size_t)NMAX * FDIM];
__device__ float g_xr[(size_t)NMAX * FDIM];   // x @ Wr^T (precomputed)
__device__ uint2 g_hfA[(size_t)NMAX * 128];   // fp16 shadow (512 halves/row)
__device__ uint2 g_hfB[(size_t)NMAX * 128];
__device__ uint4 g_ca[(size_t)NMAX * 128];    // split-bf16 h
__device__ uint4 g_cx[(size_t)NMAX * 128];    // split-bf16 x
__device__ uint4 g_cwt[512 * 128];            // split-bf16 Wt
__device__ uint4 g_cwr[512 * 128];            // split-bf16 Wr
__device__ float g_dinv[NMAX];
__device__ float g_ewself[NMAX];
__device__ int   g_cnt[NMAX];
__device__ int   g_cur[NMAX];
__device__ int   g_rp[NMAX + 1];
__device__ int2  g_edge[EMAX];
__device__ int   g_tmaxbits;   // ts > 0, monotonic, idempotent across replays

__device__ __forceinline__ float decode_scalar(const void* p) {
    int iv = *(const int*)p;
    float fv = __int_as_float(iv);
    float fa = fabsf(fv);
    if (isfinite(fv) && fa >= 1e-3f && fa <= 1e9f) return fv;
    return (float)iv;
}

// ---------------- prep ----------------
__global__ void k_prep(const float* __restrict__ ts, int e, int n, const void* gt) {
    int i = blockIdx.x * blockDim.x + threadIdx.x;
    if (i < n) { g_dinv[i] = 0.f; g_cnt[i] = 0; g_cur[i] = 0; }
    float m = -1.f;
    for (int k = i; k < e; k += gridDim.x * blockDim.x) m = fmaxf(m, ts[k]);
    if (i == 0) m = fmaxf(m, decode_scalar(gt));
    #pragma unroll
    for (int off = 16; off; off >>= 1)
        m = fmaxf(m, __shfl_xor_sync(0xffffffffu, m, off));
    if ((threadIdx.x & 31) == 0)
        atomicMax(&g_tmaxbits, __float_as_int(m));
}

__global__ void k_edge_deg(const int* __restrict__ ei, const float* __restrict__ ts, int e) {
    int i = blockIdx.x * blockDim.x + threadIdx.x;
    if (i >= e) return;
    float tmax = __int_as_float(g_tmaxbits);
    int dst = ei[e + i];
    float w = expf(-TDK * (tmax - ts[i]));
    atomicAdd(&g_dinv[dst], w);
    atomicAdd(&g_cnt[dst], 1);
}

// scan + node-finalize fused: single block, each thread owns a contiguous segment
__global__ void k_scan(int n, const void* gt) {
    __shared__ int wsum[32];
    int tid = threadIdx.x;
    int ch = (n + 1023) >> 10;
    int beg = tid * ch;
    int end = min(beg + ch, n);
    float tmax = __int_as_float(g_tmaxbits);
    float ws = expf(-TDK * (tmax - decode_scalar(gt)));
    int s = 0;
    #pragma unroll 5
    for (int i = beg; i < end; i++) {
        float d = g_dinv[i] + ws;
        float di = (d > 0.f) ? rsqrtf(d) : 0.f;
        g_dinv[i] = di;
        g_ewself[i] = di * di * ws;
        s += g_cnt[i];
    }
    int lane = tid & 31, w = tid >> 5;
    int inc = s;
    #pragma unroll
    for (int o = 1; o < 32; o <<= 1) {
        int v = __shfl_up_sync(0xffffffffu, inc, o);
        if (lane >= o) inc += v;
    }
    if (lane == 31) wsum[w] = inc;
    __syncthreads();
    if (w == 0) {
        int v = wsum[lane];
        int wi = v;
        #pragma unroll
        for (int o = 1; o < 32; o <<= 1) {
            int u = __shfl_up_sync(0xffffffffu, wi, o);
            if (lane >= o) wi += u;
        }
        wsum[lane] = wi - v;
    }
    __syncthreads();
    int excl = wsum[w] + inc - s;
    int run = excl;
    #pragma unroll 5
    for (int i = beg; i < end; i++) {
        int c = g_cnt[i];
        g_rp[i] = run;
        run += c;
    }
    if (tid == 1023) g_rp[n] = excl + s;
}

__global__ void k_scatter(const int* __restrict__ ei, const float* __restrict__ ts, int e) {
    int i = blockIdx.x * blockDim.x + threadIdx.x;
    if (i >= e) return;
    float tmax = __int_as_float(g_tmaxbits);
    int src = ei[i];
    int dst = ei[e + i];
    float w = expf(-TDK * (tmax - ts[i]));
    int pos = g_rp[dst] + atomicAdd(&g_cur[dst], 1);
    g_edge[pos] = make_int2(src, __float_as_int(g_dinv[src] * w * g_dinv[dst]));
}

// ================= split-bf16 helpers =================
__device__ __forceinline__ uint32_t bsplit2(float x, float y, uint32_t& t2) {
    __nv_bfloat16 hx = __float2bfloat16_rn(x);
    __nv_bfloat16 hy = __float2bfloat16_rn(y);
    float rx = x - __bfloat162float(hx);
    float ry = y - __bfloat162float(hy);
    __nv_bfloat16 lx = __float2bfloat16_rn(rx);
    __nv_bfloat16 ly = __float2bfloat16_rn(ry);
    t2 = (uint32_t)__bfloat16_as_ushort(lx) | ((uint32_t)__bfloat16_as_ushort(ly) << 16);
    return (uint32_t)__bfloat16_as_ushort(hx) | ((uint32_t)__bfloat16_as_ushort(hy) << 16);
}

__device__ __forceinline__ void cvt_one(const float* __restrict__ in,
                                        uint4* __restrict__ out, int idx) {
    int row = idx >> 6;
    int rem = idx & 63;
    int kc = rem >> 1;
    int h = rem & 1;
    const float* p = in + (size_t)row * FDIM + kc * 16 + 4 * h;
    float4 v0 = *(const float4*)(p);
    float4 v1 = *(const float4*)(p + 8);
    uint32_t l0, l1, l4, l5;
    uint32_t h0 = bsplit2(v0.x, v0.y, l0);
    uint32_t h1 = bsplit2(v0.z, v0.w, l1);
    uint32_t h4 = bsplit2(v1.x, v1.y, l4);
    uint32_t h5 = bsplit2(v1.z, v1.w, l5);
    size_t ob = (size_t)row * 128 + kc * 4 + 2 * h;
    out[ob]     = make_uint4(h0, h4, l0, l4);
    out[ob + 1] = make_uint4(h1, h5, l1, l5);
}

// all three input conversions (Wt, Wr, x) in one kernel
__global__ void k_cvtw3(const float* __restrict__ Wt, const float* __restrict__ Wr,
                        const float* __restrict__ x, uint4* __restrict__ cwt,
                        uint4* __restrict__ cwr, uint4* __restrict__ cx, int nx) {
    int idx = blockIdx.x * blockDim.x + threadIdx.x;
    const int half = 512 * 64;
    if (idx < half) cvt_one(Wt, cwt, idx);
    else if (idx < 2 * half) cvt_one(Wr, cwr, idx - half);
    else if (idx < 2 * half + nx) cvt_one(x, cx, idx - 2 * half);
}

// ------- diffusion: warp-per-node, fp32 state -------
// G16: gather from fp16 shadow (else fp32 hin).
// SOUT: 0 = write fp32 hout + fp16 hfout; 1 = write split-bf16 cout only (final step).
template <int G16, int SOUT>
__global__ __launch_bounds__(256)
void k_diff(const float4* __restrict__ hin, const uint2* __restrict__ hfin,
            float4* __restrict__ hout, uint2* __restrict__ hfout,
            uint4* __restrict__ cout, int n) {
    __shared__ int2 se[8][32];
    int wid = threadIdx.x >> 5, lane = threadIdx.x & 31;
    int v = blockIdx.x * 8 + wid;
    if (v >= n) return;
    int b = g_rp[v], e2 = g_rp[v + 1];
    float4 a0 = make_float4(0.f, 0.f, 0.f, 0.f);
    float4 a1 = a0, a2 = a0, a3 = a0;
    for (int c = b; c < e2; c += 32) {
        int m = min(32, e2 - c);
        if (lane < m) se[wid][lane] = __ldg(&g_edge[c + lane]);
        __syncwarp();
        #pragma unroll 4
        for (int i = 0; i < m; i++) {
            int2 ed = se[wid][i];
            float w = __int_as_float(ed.y);
            if (G16) {
                const uint2* hp = hfin + (size_t)ed.x * 128 + lane;
                uint2 q0 = __ldg(hp);
                uint2 q1 = __ldg(hp + 32);
                uint2 q2 = __ldg(hp + 64);
                uint2 q3 = __ldg(hp + 96);
                float2 f;
                f = __half22float2(*(__half2*)&q0.x);
                a0.x = fmaf(w, f.x, a0.x); a0.y = fmaf(w, f.y, a0.y);
                f = __half22float2(*(__half2*)&q0.y);
                a0.z = fmaf(w, f.x, a0.z); a0.w = fmaf(w, f.y, a0.w);
                f = __half22float2(*(__half2*)&q1.x);
                a1.x = fmaf(w, f.x, a1.x); a1.y = fmaf(w, f.y, a1.y);
                f = __half22float2(*(__half2*)&q1.y);
                a1.z = fmaf(w, f.x, a1.z); a1.w = fmaf(w, f.y, a1.w);
                f = __half22float2(*(__half2*)&q2.x);
                a2.x = fmaf(w, f.x, a2.x); a2.y = fmaf(w, f.y, a2.y);
                f = __half22float2(*(__half2*)&q2.y);
                a2.z = fmaf(w, f.x, a2.z); a2.w = fmaf(w, f.y, a2.w);
                f = __half22float2(*(__half2*)&q3.x);
                a3.x = fmaf(w, f.x, a3.x); a3.y = fmaf(w, f.y, a3.y);
                f = __half22float2(*(__half2*)&q3.y);
                a3.z = fmaf(w, f.x, a3.z); a3.w = fmaf(w, f.y, a3.w);
            } else {
                const float4* hp = hin + (size_t)ed.x * F4 + lane;
                float4 v0 = __ldg(hp);
                float4 v1 = __ldg(hp + 32);
                float4 v2 = __ldg(hp + 64);
                float4 v3 = __ldg(hp + 96);
                a0.x = fmaf(w, v0.x, a0.x); a0.y = fmaf(w, v0.y, a0.y);
                a0.z = fmaf(w, v0.z, a0.z); a0.w = fmaf(w, v0.w, a0.w);
                a1.x = fmaf(w, v1.x, a1.x); a1.y = fmaf(w, v1.y, a1.y);
                a1.z = fmaf(w, v1.z, a1.z); a1.w = fmaf(w, v1.w, a1.w);
                a2.x = fmaf(w, v2.x, a2.x); a2.y = fmaf(w, v2.y, a2.y);
                a2.z = fmaf(w, v2.z, a2.z); a2.w = fmaf(w, v2.w, a2.w);
                a3.x = fmaf(w, v3.x, a3.x); a3.y = fmaf(w, v3.y, a3.y);
                a3.z = fmaf(w, v3.z, a3.z); a3.w = fmaf(w, v3.w, a3.w);
            }
        }
        __syncwarp();
    }
    float cs = (1.f - DT) + DT * g_ewself[v];
    const float4* sp = hin + (size_t)v * F4 + lane;
    float4 s0 = __ldg(sp), s1 = __ldg(sp + 32), s2 = __ldg(sp + 64), s3 = __ldg(sp + 96);
    float4 og[4];
    og[0].x = cs * s0.x + DT * a0.x; og[0].y = cs * s0.y + DT * a0.y;
    og[0].z = cs * s0.z + DT * a0.z; og[0].w = cs * s0.w + DT * a0.w;
    og[1].x = cs * s1.x + DT * a1.x; og[1].y = cs * s1.y + DT * a1.y;
    og[1].z = cs * s1.z + DT * a1.z; og[1].w = cs * s1.w + DT * a1.w;
    og[2].x = cs * s2.x + DT * a2.x; og[2].y = cs * s2.y + DT * a2.y;
    og[2].z = cs * s2.z + DT * a2.z; og[2].w = cs * s2.w + DT * a2.w;
    og[3].x = cs * s3.x + DT * a3.x; og[3].y = cs * s3.y + DT * a3.y;
    og[3].z = cs * s3.z + DT * a3.z; og[3].w = cs * s3.w + DT * a3.w;

    if (!SOUT) {
        float4* op = hout + (size_t)v * F4 + lane;
        uint2* fp = hfout + (size_t)v * 128 + lane;
        #pragma unroll
        for (int j = 0; j < 4; j++) {
            op[j * 32] = og[j];
            __half2 p0 = __floats2half2_rn(og[j].x, og[j].y);
            __half2 p1 = __floats2half2_rn(og[j].z, og[j].w);
            fp[j * 32] = make_uint2(*(uint32_t*)&p0, *(uint32_t*)&p1);
        }
    } else {
        // emit split-bf16 in GEMM layout directly (lane-pair repack via shfl)
        int m = lane & 3;
        #pragma unroll
        for (int j = 0; j < 4; j++) {
            uint32_t w01l, w23l;
            uint32_t w01h = bsplit2(og[j].x, og[j].y, w01l);
            uint32_t w23h = bsplit2(og[j].z, og[j].w, w23l);
            uint32_t p01h = __shfl_xor_sync(0xffffffffu, w01h, 2);
            uint32_t p01l = __shfl_xor_sync(0xffffffffu, w01l, 2);
            uint32_t p23h = __shfl_xor_sync(0xffffffffu, w23h, 2);
            uint32_t p23l = __shfl_xor_sync(0xffffffffu, w23l, 2);
            int kc = (lane >> 2) + 8 * j;
            size_t ob = (size_t)v * 128 + kc * 4;
            if (m < 2)
                cout[ob + 2 * m] = make_uint4(w01h, p01h, w01l, p01l);
            else
                cout[ob + 2 * m - 3] = make_uint4(p23h, w23h, p23l, w23l);
        }
    }
}

// ================= mma.sync bf16 split SGEMM =================
// KCH=32 per pipeline stage (2 sub-chunks of 16); 3-stage cp.async ring.
#define NSTG  16
#define SMEMB 98304
#define SB2(s, mat, c, row, q) \
    sbuf[((((((s) * 2 + (mat)) * 2 + (c)) * 128 + (row))) << 2) + (q)]

__device__ __forceinline__ uint32_t smem_u32(const void* p) {
    uint32_t a;
    asm("{ .reg .u64 t; cvta.to.shared.u64 t, %1; cvt.u32.u64 %0, t; }" : "=r"(a) : "l"(p));
    return a;
}
__device__ __forceinline__ void cp16(uint32_t d, const void* s) {
    asm volatile("cp.async.cg.shared.global [%0], [%1], 16;" :: "r"(d), "l"(s));
}
__device__ __forceinline__ void cp_commit() {
    asm volatile("cp.async.commit_group;" ::: "memory");
}
__device__ __forceinline__ void cp_wait1() {
    asm volatile("cp.async.wait_group 1;" ::: "memory");
}
__device__ __forceinline__ void cp_wait0() {
    asm volatile("cp.async.wait_group 0;" ::: "memory");
}

__device__ __forceinline__ void mma_bf16(float* d, const uint32_t* a, const uint32_t* b) {
    asm volatile(
        "mma.sync.aligned.m16n8k16.row.col.f32.bf16.bf16.f32 "
        "{%0,%1,%2,%3}, {%4,%5,%6,%7}, {%8,%9}, {%0,%1,%2,%3};"
        : "+f"(d[0]), "+f"(d[1]), "+f"(d[2]), "+f"(d[3])
        : "r"(a[0]), "r"(a[1]), "r"(a[2]), "r"(a[3]), "r"(b[0]), "r"(b[1]));
}

// MODE 2: C = A*B^T ;  MODE 3: C = relu(A*B^T + bias[n]) + R[m][n]
template <int MODE>
__global__ __launch_bounds__(256, 1)
void k_gemm_mma(const uint4* __restrict__ A4, const uint4* __restrict__ B4,
                const float* __restrict__ bias, const float* __restrict__ R,
                float* __restrict__ C, int M) {
    extern __shared__ uint4 sbuf[];
    int tid = threadIdx.x;
    int lane = tid & 31, wid = tid >> 5;
    int warpM = wid >> 2;
    int warpN = wid & 3;
    int g = lane >> 2, t = lane & 3;
    int m0 = blockIdx.y * 128;
    int n0 = blockIdx.x * 128;

    int lr = tid >> 1;
    int h = tid & 1;
    const uint4* Ag = A4 + (size_t)(m0 + lr) * 128 + 2 * h;
    const uint4* Bg = B4 + (size_t)(n0 + lr) * 128 + 2 * h;

    float acc[4][4][4];
    #pragma unroll
    for (int i = 0; i < 4; i++)
        #pragma unroll
        for (int j = 0; j < 4; j++)
            #pragma unroll
            for (int k = 0; k < 4; k++) acc[i][j][k] = 0.f;

    // prologue: stages 0,1 (chunks 0..3)
    #pragma unroll
    for (int p = 0; p < 2; p++) {
        #pragma unroll
        for (int c = 0; c < 2; c++) {
            int kc = p * 2 + c;
            uint32_t da = smem_u32(&SB2(p, 0, c, lr, 2 * h));
            uint32_t db = smem_u32(&SB2(p, 1, c, lr, 2 * h));
            cp16(da, Ag + kc * 4);      cp16(da + 16, Ag + kc * 4 + 1);
            cp16(db, Bg + kc * 4);      cp16(db + 16, Bg + kc * 4 + 1);
        }
        cp_commit();
    }

    int arow = warpM * 64 + g;
    int bn = warpN * 32 + g;

    for (int st = 0; st < NSTG; st++) {
        if (st >= NSTG - 2) cp_wait0(); else cp_wait1();
        __syncthreads();

        if (st + 2 < NSTG) {
            int ps = (st + 2) % 3;
            #pragma unroll
            for (int c = 0; c < 2; c++) {
                int kc = (st + 2) * 2 + c;
                uint32_t da = smem_u32(&SB2(ps, 0, c, lr, 2 * h));
                uint32_t db = smem_u32(&SB2(ps, 1, c, lr, 2 * h));
                cp16(da, Ag + kc * 4);  cp16(da + 16, Ag + kc * 4 + 1);
                cp16(db, Bg + kc * 4);  cp16(db + 16, Bg + kc * 4 + 1);
            }
            cp_commit();
        }

        int s = st % 3;
        #pragma unroll
        for (int c = 0; c < 2; c++) {
            uint32_t a1[4][4], a2[4][4], b1[4][2], b2[4][2];
            #pragma unroll
            for (int mt = 0; mt < 4; mt++) {
                uint4 va  = SB2(s, 0, c, arow + mt * 16, t);
                uint4 va8 = SB2(s, 0, c, arow + mt * 16 + 8, t);
                a1[mt][0] = va.x; a1[mt][1] = va8.x; a1[mt][2] = va.y; a1[mt][3] = va8.y;
                a2[mt][0] = va.z; a2[mt][1] = va8.z; a2[mt][2] = va.w; a2[mt][3] = va8.w;
            }
            #pragma unroll
            for (int nt = 0; nt < 4; nt++) {
                uint4 vb = SB2(s, 1, c, bn + nt * 8, t);
                b1[nt][0] = vb.x; b1[nt][1] = vb.y;
                b2[nt][0] = vb.z; b2[nt][1] = vb.w;
            }
            #pragma unroll
            for (int mt = 0; mt < 4; mt++)
                #pragma unroll
                for (int nt = 0; nt < 4; nt++) {
                    mma_bf16(acc[mt][nt], a1[mt], b1[nt]);
                    mma_bf16(acc[mt][nt], a1[mt], b2[nt]);
                    mma_bf16(acc[mt][nt], a2[mt], b1[nt]);
                }
        }
    }

    #pragma unroll
    for (int mt = 0; mt < 4; mt++) {
        int row0 = m0 + warpM * 64 + mt * 16 + g;
        #pragma unroll
        for (int half = 0; half < 2; half++) {
            int row = row0 + half * 8;
            if (row >= M) continue;
            #pragma unroll
            for (int nt = 0; nt < 4; nt++) {
                int col = n0 + warpN * 32 + nt * 8 + t * 2;
                float v0 = acc[mt][nt][half * 2 + 0];
                float v1 = acc[mt][nt][half * 2 + 1];
                if (MODE == 3) {
                    float2 bb = *(const float2*)&bias[col];
                    float2 rr = *(const float2*)&R[(size_t)row * FDIM + col];
                    v0 = fmaxf(v0 + bb.x, 0.f) + rr.x;
                    v1 = fmaxf(v1 + bb.y, 0.f) + rr.y;
                }
                *(float2*)&C[(size_t)row * FDIM + col] = make_float2(v0, v1);
            }
        }
    }
}

// ---------------- layernorm ----------------
__global__ void k_ln(float* __restrict__ io, const float* __restrict__ gamma,
                     const float* __restrict__ beta) {
    int r = blockIdx.x;
    int t = threadIdx.x;
    float4* row = ((float4*)io) + (size_t)r * F4;
    float4 v = row[t];
    float s = v.x + v.y + v.z + v.w;
    float q = v.x * v.x + v.y * v.y + v.z * v.z + v.w * v.w;
    #pragma unroll
    for (int off = 16; off; off >>= 1) {
        s += __shfl_xor_sync(0xffffffffu, s, off);
        q += __shfl_xor_sync(0xffffffffu, q, off);
    }
    __shared__ float ss[4], sq[4];
    if ((t & 31) == 0) { ss[t >> 5] = s; sq[t >> 5] = q; }
    __syncthreads();
    s = ss[0] + ss[1] + ss[2] + ss[3];
    q = sq[0] + sq[1] + sq[2] + sq[3];
    float mu = s * (1.f / FDIM);
    float var = q * (1.f / FDIM) - mu * mu;
    float inv = rsqrtf(var + LNEPS);
    float4 g = ((const float4*)gamma)[t];
    float4 bb = ((const float4*)beta)[t];
    v.x = (v.x - mu) * inv * g.x + bb.x;
    v.y = (v.y - mu) * inv * g.y + bb.y;
    v.z = (v.z - mu) * inv * g.z + bb.z;
    v.w = (v.w - mu) * inv * g.w + bb.w;
    row[t] = v;
}

// ---------------- launch ----------------
extern "C" void kernel_launch(void* const* d_in, const int* in_sizes, int n_in,
                              void* d_out, int out_size) {
    const float* x     = (const float*)d_in[0];
    const int*   ei    = (const int*)d_in[1];
    const float* ts    = (const float*)d_in[2];
    const float* Wt    = (const float*)d_in[3];
    const float* bt    = (const float*)d_in[4];
    const float* Wr    = (const float*)d_in[5];
    const float* gamma = (const float*)d_in[6];
    const float* beta  = (const float*)d_in[7];
    const void*  gt    = d_in[8];

    int n = in_sizes[0] / FDIM;
    int e = in_sizes[1] / 2;

    float *h0, *h1, *xr;
    uint2 *hfA, *hfB;
    uint4 *ca, *cx, *cwt, *cwr;
    cudaGetSymbolAddress((void**)&h0, g_h0);
    cudaGetSymbolAddress((void**)&h1, g_h1);
    cudaGetSymbolAddress((void**)&xr, g_xr);
    cudaGetSymbolAddress((void**)&hfA, g_hfA);
    cudaGetSymbolAddress((void**)&hfB, g_hfB);
    cudaGetSymbolAddress((void**)&ca, g_ca);
    cudaGetSymbolAddress((void**)&cx, g_cx);
    cudaGetSymbolAddress((void**)&cwt, g_cwt);
    cudaGetSymbolAddress((void**)&cwr, g_cwr);

    cudaFuncSetAttribute(k_gemm_mma<2>, cudaFuncAttributeMaxDynamicSharedMemorySize, SMEMB);
    cudaFuncSetAttribute(k_gemm_mma<3>, cudaFuncAttributeMaxDynamicSharedMemorySize, SMEMB);

    const int tb = 256;
    dim3 gg(FDIM / 128, (n + 127) / 128);   // (4, 157)
    int gb = (n + 7) / 8;

    // launch index 3 = plain GEMM (profiled by ncu -s 5 -c 1)
    k_cvtw3<<<(2 * 512 * 64 + n * 64 + tb - 1) / tb, tb>>>(Wt, Wr, x, cwt, cwr, cx, n * 64);
    k_prep<<<(n + tb - 1) / tb, tb>>>(ts, e, n, gt);
    k_edge_deg<<<(e + tb - 1) / tb, tb>>>(ei, ts, e);
    k_gemm_mma<2><<<gg, 256, SMEMB>>>(cx, cwr, nullptr, nullptr, xr, n);  // xr = x@Wr^T

    k_scan<<<1, 1024>>>(n, gt);
    k_scatter<<<(e + tb - 1) / tb, tb>>>(ei, ts, e);

    // 5 Euler diffusion steps; step 1 gathers fp32 x, step 5 emits split-bf16
    k_diff<0, 0><<<gb, 256>>>((const float4*)x,  nullptr, (float4*)h1, hfB, nullptr, n);
    k_diff<1, 0><<<gb, 256>>>((const float4*)h1, hfB, (float4*)h0, hfA, nullptr, n);
    k_diff<1, 0><<<gb, 256>>>((const float4*)h0, hfA, (float4*)h1, hfB, nullptr, n);
    k_diff<1, 0><<<gb, 256>>>((const float4*)h1, hfB, (float4*)h0, hfA, nullptr, n);
    k_diff<1, 1><<<gb, 256>>>((const float4*)h0, hfA, nullptr, nullptr, ca, n);

    float* out = (float*)d_out;
    k_gemm_mma<3><<<gg, 256, SMEMB>>>(ca, cwt, bt, xr, out, n);  // out = relu(h@Wt^T+b)+xr
    k_ln<<<n, 128>>>(out, gamma, beta);
}

// round 17
// speedup vs baseline: 1.0876x; 1.0434x over previous
#include <cuda_runtime.h>
#include <cuda_bf16.h>
#include <cuda_fp16.h>
#include <math.h>
#include <stdint.h>

#define FDIM 512
#define F4   128
#define NMAX 20608
#define EMAX 335872
#define TDK  0.1f
#define DT   0.2f
#define LNEPS 1e-5f

// ---------------- device scratch ----------------
__device__ float g_h0[(size_t)NMAX * FDIM];
__device__ float g_h1[(size_t)NMAX * FDIM];
__device__ float g_xr[(size_t)NMAX * FDIM];   // x @ Wr^T (precomputed)
__device__ uint2 g_hfA[(size_t)NMAX * 128];   // fp16 shadow (512 halves/row)
__device__ uint2 g_hfB[(size_t)NMAX * 128];
__device__ uint4 g_ca[(size_t)NMAX * 128];    // split-bf16 h
__device__ uint4 g_cx[(size_t)NMAX * 128];    // split-bf16 x
__device__ uint4 g_cwt[512 * 128];            // split-bf16 Wt
__device__ uint4 g_cwr[512 * 128];            // split-bf16 Wr
__device__ float g_dinv[NMAX];
__device__ float g_ewself[NMAX];
__device__ int   g_cnt[NMAX];
__device__ int   g_cur[NMAX];
__device__ int   g_rp[NMAX + 1];
__device__ int2  g_edge[EMAX];
__device__ int   g_tmaxbits;   // ts > 0, monotonic, idempotent across replays

__device__ __forceinline__ float decode_scalar(const void* p) {
    int iv = *(const int*)p;
    float fv = __int_as_float(iv);
    float fa = fabsf(fv);
    if (isfinite(fv) && fa >= 1e-3f && fa <= 1e9f) return fv;
    return (float)iv;
}

// ---------------- prep ----------------
__global__ void k_prep(const float* __restrict__ ts, int e, int n, const void* gt) {
    int i = blockIdx.x * blockDim.x + threadIdx.x;
    if (i < n) { g_dinv[i] = 0.f; g_cnt[i] = 0; g_cur[i] = 0; }
    float m = -1.f;
    for (int k = i; k < e; k += gridDim.x * blockDim.x) m = fmaxf(m, ts[k]);
    if (i == 0) m = fmaxf(m, decode_scalar(gt));
    #pragma unroll
    for (int off = 16; off; off >>= 1)
        m = fmaxf(m, __shfl_xor_sync(0xffffffffu, m, off));
    if ((threadIdx.x & 31) == 0)
        atomicMax(&g_tmaxbits, __float_as_int(m));
}

__global__ void k_edge_deg(const int* __restrict__ ei, const float* __restrict__ ts, int e) {
    int i = blockIdx.x * blockDim.x + threadIdx.x;
    if (i >= e) return;
    float tmax = __int_as_float(g_tmaxbits);
    int dst = ei[e + i];
    float w = expf(-TDK * (tmax - ts[i]));
    atomicAdd(&g_dinv[dst], w);
    atomicAdd(&g_cnt[dst], 1);
}

// scan + node-finalize fused: single block, each thread owns a contiguous segment
__global__ void k_scan(int n, const void* gt) {
    __shared__ int wsum[32];
    int tid = threadIdx.x;
    int ch = (n + 1023) >> 10;
    int beg = tid * ch;
    int end = min(beg + ch, n);
    float tmax = __int_as_float(g_tmaxbits);
    float ws = expf(-TDK * (tmax - decode_scalar(gt)));
    int s = 0;
    #pragma unroll 5
    for (int i = beg; i < end; i++) {
        float d = g_dinv[i] + ws;
        float di = (d > 0.f) ? rsqrtf(d) : 0.f;
        g_dinv[i] = di;
        g_ewself[i] = di * di * ws;
        s += g_cnt[i];
    }
    int lane = tid & 31, w = tid >> 5;
    int inc = s;
    #pragma unroll
    for (int o = 1; o < 32; o <<= 1) {
        int v = __shfl_up_sync(0xffffffffu, inc, o);
        if (lane >= o) inc += v;
    }
    if (lane == 31) wsum[w] = inc;
    __syncthreads();
    if (w == 0) {
        int v = wsum[lane];
        int wi = v;
        #pragma unroll
        for (int o = 1; o < 32; o <<= 1) {
            int u = __shfl_up_sync(0xffffffffu, wi, o);
            if (lane >= o) wi += u;
        }
        wsum[lane] = wi - v;
    }
    __syncthreads();
    int excl = wsum[w] + inc - s;
    int run = excl;
    #pragma unroll 5
    for (int i = beg; i < end; i++) {
        int c = g_cnt[i];
        g_rp[i] = run;
        run += c;
    }
    if (tid == 1023) g_rp[n] = excl + s;
}

__global__ void k_scatter(const int* __restrict__ ei, const float* __restrict__ ts, int e) {
    int i = blockIdx.x * blockDim.x + threadIdx.x;
    if (i >= e) return;
    float tmax = __int_as_float(g_tmaxbits);
    int src = ei[i];
    int dst = ei[e + i];
    float w = expf(-TDK * (tmax - ts[i]));
    int pos = g_rp[dst] + atomicAdd(&g_cur[dst], 1);
    g_edge[pos] = make_int2(src, __float_as_int(g_dinv[src] * w * g_dinv[dst]));
}

// ================= split-bf16 helpers =================
__device__ __forceinline__ uint32_t bsplit2(float x, float y, uint32_t& t2) {
    __nv_bfloat16 hx = __float2bfloat16_rn(x);
    __nv_bfloat16 hy = __float2bfloat16_rn(y);
    float rx = x - __bfloat162float(hx);
    float ry = y - __bfloat162float(hy);
    __nv_bfloat16 lx = __float2bfloat16_rn(rx);
    __nv_bfloat16 ly = __float2bfloat16_rn(ry);
    t2 = (uint32_t)__bfloat16_as_ushort(lx) | ((uint32_t)__bfloat16_as_ushort(ly) << 16);
    return (uint32_t)__bfloat16_as_ushort(hx) | ((uint32_t)__bfloat16_as_ushort(hy) << 16);
}

__device__ __forceinline__ void cvt_one(const float* __restrict__ in,
                                        uint4* __restrict__ out, int idx) {
    int row = idx >> 6;
    int rem = idx & 63;
    int kc = rem >> 1;
    int h = rem & 1;
    const float* p = in + (size_t)row * FDIM + kc * 16 + 4 * h;
    float4 v0 = *(const float4*)(p);
    float4 v1 = *(const float4*)(p + 8);
    uint32_t l0, l1, l4, l5;
    uint32_t h0 = bsplit2(v0.x, v0.y, l0);
    uint32_t h1 = bsplit2(v0.z, v0.w, l1);
    uint32_t h4 = bsplit2(v1.x, v1.y, l4);
    uint32_t h5 = bsplit2(v1.z, v1.w, l5);
    size_t ob = (size_t)row * 128 + kc * 4 + 2 * h;
    out[ob]     = make_uint4(h0, h4, l0, l4);
    out[ob + 1] = make_uint4(h1, h5, l1, l5);
}

// all three input conversions (Wt, Wr, x) in one kernel
__global__ void k_cvtw3(const float* __restrict__ Wt, const float* __restrict__ Wr,
                        const float* __restrict__ x, uint4* __restrict__ cwt,
                        uint4* __restrict__ cwr, uint4* __restrict__ cx, int nx) {
    int idx = blockIdx.x * blockDim.x + threadIdx.x;
    const int half = 512 * 64;
    if (idx < half) cvt_one(Wt, cwt, idx);
    else if (idx < 2 * half) cvt_one(Wr, cwr, idx - half);
    else if (idx < 2 * half + nx) cvt_one(x, cx, idx - 2 * half);
}

// ------- diffusion: warp-per-node, fp32 state -------
// G16: gather from fp16 shadow (else fp32 hin).
// SOUT: 0 = write fp32 hout + fp16 hfout; 1 = write split-bf16 cout only (final step).
template <int G16, int SOUT>
__global__ __launch_bounds__(256)
void k_diff(const float4* __restrict__ hin, const uint2* __restrict__ hfin,
            float4* __restrict__ hout, uint2* __restrict__ hfout,
            uint4* __restrict__ cout, int n) {
    __shared__ int2 se[8][32];
    int wid = threadIdx.x >> 5, lane = threadIdx.x & 31;
    int v = blockIdx.x * 8 + wid;
    if (v >= n) return;
    int b = g_rp[v], e2 = g_rp[v + 1];
    float4 a0 = make_float4(0.f, 0.f, 0.f, 0.f);
    float4 a1 = a0, a2 = a0, a3 = a0;
    for (int c = b; c < e2; c += 32) {
        int m = min(32, e2 - c);
        if (lane < m) se[wid][lane] = __ldg(&g_edge[c + lane]);
        __syncwarp();
        #pragma unroll 4
        for (int i = 0; i < m; i++) {
            int2 ed = se[wid][i];
            float w = __int_as_float(ed.y);
            if (G16) {
                const uint2* hp = hfin + (size_t)ed.x * 128 + lane;
                uint2 q0 = __ldg(hp);
                uint2 q1 = __ldg(hp + 32);
                uint2 q2 = __ldg(hp + 64);
                uint2 q3 = __ldg(hp + 96);
                float2 f;
                f = __half22float2(*(__half2*)&q0.x);
                a0.x = fmaf(w, f.x, a0.x); a0.y = fmaf(w, f.y, a0.y);
                f = __half22float2(*(__half2*)&q0.y);
                a0.z = fmaf(w, f.x, a0.z); a0.w = fmaf(w, f.y, a0.w);
                f = __half22float2(*(__half2*)&q1.x);
                a1.x = fmaf(w, f.x, a1.x); a1.y = fmaf(w, f.y, a1.y);
                f = __half22float2(*(__half2*)&q1.y);
                a1.z = fmaf(w, f.x, a1.z); a1.w = fmaf(w, f.y, a1.w);
                f = __half22float2(*(__half2*)&q2.x);
                a2.x = fmaf(w, f.x, a2.x); a2.y = fmaf(w, f.y, a2.y);
                f = __half22float2(*(__half2*)&q2.y);
                a2.z = fmaf(w, f.x, a2.z); a2.w = fmaf(w, f.y, a2.w);
                f = __half22float2(*(__half2*)&q3.x);
                a3.x = fmaf(w, f.x, a3.x); a3.y = fmaf(w, f.y, a3.y);
                f = __half22float2(*(__half2*)&q3.y);
                a3.z = fmaf(w, f.x, a3.z); a3.w = fmaf(w, f.y, a3.w);
            } else {
                const float4* hp = hin + (size_t)ed.x * F4 + lane;
                float4 v0 = __ldg(hp);
                float4 v1 = __ldg(hp + 32);
                float4 v2 = __ldg(hp + 64);
                float4 v3 = __ldg(hp + 96);
                a0.x = fmaf(w, v0.x, a0.x); a0.y = fmaf(w, v0.y, a0.y);
                a0.z = fmaf(w, v0.z, a0.z); a0.w = fmaf(w, v0.w, a0.w);
                a1.x = fmaf(w, v1.x, a1.x); a1.y = fmaf(w, v1.y, a1.y);
                a1.z = fmaf(w, v1.z, a1.z); a1.w = fmaf(w, v1.w, a1.w);
                a2.x = fmaf(w, v2.x, a2.x); a2.y = fmaf(w, v2.y, a2.y);
                a2.z = fmaf(w, v2.z, a2.z); a2.w = fmaf(w, v2.w, a2.w);
                a3.x = fmaf(w, v3.x, a3.x); a3.y = fmaf(w, v3.y, a3.y);
                a3.z = fmaf(w, v3.z, a3.z); a3.w = fmaf(w, v3.w, a3.w);
            }
        }
        __syncwarp();
    }
    float cs = (1.f - DT) + DT * g_ewself[v];
    const float4* sp = hin + (size_t)v * F4 + lane;
    float4 s0 = __ldg(sp), s1 = __ldg(sp + 32), s2 = __ldg(sp + 64), s3 = __ldg(sp + 96);
    float4 og[4];
    og[0].x = cs * s0.x + DT * a0.x; og[0].y = cs * s0.y + DT * a0.y;
    og[0].z = cs * s0.z + DT * a0.z; og[0].w = cs * s0.w + DT * a0.w;
    og[1].x = cs * s1.x + DT * a1.x; og[1].y = cs * s1.y + DT * a1.y;
    og[1].z = cs * s1.z + DT * a1.z; og[1].w = cs * s1.w + DT * a1.w;
    og[2].x = cs * s2.x + DT * a2.x; og[2].y = cs * s2.y + DT * a2.y;
    og[2].z = cs * s2.z + DT * a2.z; og[2].w = cs * s2.w + DT * a2.w;
    og[3].x = cs * s3.x + DT * a3.x; og[3].y = cs * s3.y + DT * a3.y;
    og[3].z = cs * s3.z + DT * a3.z; og[3].w = cs * s3.w + DT * a3.w;

    if (!SOUT) {
        float4* op = hout + (size_t)v * F4 + lane;
        uint2* fp = hfout + (size_t)v * 128 + lane;
        #pragma unroll
        for (int j = 0; j < 4; j++) {
            op[j * 32] = og[j];
            __half2 p0 = __floats2half2_rn(og[j].x, og[j].y);
            __half2 p1 = __floats2half2_rn(og[j].z, og[j].w);
            fp[j * 32] = make_uint2(*(uint32_t*)&p0, *(uint32_t*)&p1);
        }
    } else {
        // emit split-bf16 in GEMM layout directly (lane-pair repack via shfl)
        int m = lane & 3;
        #pragma unroll
        for (int j = 0; j < 4; j++) {
            uint32_t w01l, w23l;
            uint32_t w01h = bsplit2(og[j].x, og[j].y, w01l);
            uint32_t w23h = bsplit2(og[j].z, og[j].w, w23l);
            uint32_t p01h = __shfl_xor_sync(0xffffffffu, w01h, 2);
            uint32_t p01l = __shfl_xor_sync(0xffffffffu, w01l, 2);
            uint32_t p23h = __shfl_xor_sync(0xffffffffu, w23h, 2);
            uint32_t p23l = __shfl_xor_sync(0xffffffffu, w23l, 2);
            int kc = (lane >> 2) + 8 * j;
            size_t ob = (size_t)v * 128 + kc * 4;
            if (m < 2)
                cout[ob + 2 * m] = make_uint4(w01h, p01h, w01l, p01l);
            else
                cout[ob + 2 * m - 3] = make_uint4(p23h, w23h, p23l, w23l);
        }
    }
}

// ================= mma.sync bf16 split SGEMM =================
// KCH=32 per pipeline stage (2 sub-chunks of 16); 3-stage cp.async ring.
#define NSTG  16
#define SMEMB 98304
#define SB2(s, mat, c, row, q) \
    sbuf[((((((s) * 2 + (mat)) * 2 + (c)) * 128 + (row))) << 2) + (q)]

__device__ __forceinline__ uint32_t smem_u32(const void* p) {
    uint32_t a;
    asm("{ .reg .u64 t; cvta.to.shared.u64 t, %1; cvt.u32.u64 %0, t; }" : "=r"(a) : "l"(p));
    return a;
}
__device__ __forceinline__ void cp16(uint32_t d, const void* s) {
    asm volatile("cp.async.cg.shared.global [%0], [%1], 16;" :: "r"(d), "l"(s));
}
__device__ __forceinline__ void cp_commit() {
    asm volatile("cp.async.commit_group;" ::: "memory");
}
__device__ __forceinline__ void cp_wait1() {
    asm volatile("cp.async.wait_group 1;" ::: "memory");
}
__device__ __forceinline__ void cp_wait0() {
    asm volatile("cp.async.wait_group 0;" ::: "memory");
}

__device__ __forceinline__ void mma_bf16(float* d, const uint32_t* a, const uint32_t* b) {
    asm volatile(
        "mma.sync.aligned.m16n8k16.row.col.f32.bf16.bf16.f32 "
        "{%0,%1,%2,%3}, {%4,%5,%6,%7}, {%8,%9}, {%0,%1,%2,%3};"
        : "+f"(d[0]), "+f"(d[1]), "+f"(d[2]), "+f"(d[3])
        : "r"(a[0]), "r"(a[1]), "r"(a[2]), "r"(a[3]), "r"(b[0]), "r"(b[1]));
}

// MODE 2: C = A*B^T ;  MODE 3: C = relu(A*B^T + bias[n]) + R[m][n]
template <int MODE>
__global__ __launch_bounds__(256, 1)
void k_gemm_mma(const uint4* __restrict__ A4, const uint4* __restrict__ B4,
                const float* __restrict__ bias, const float* __restrict__ R,
                float* __restrict__ C, int M) {
    extern __shared__ uint4 sbuf[];
    int tid = threadIdx.x;
    int lane = tid & 31, wid = tid >> 5;
    int warpM = wid >> 2;
    int warpN = wid & 3;
    int g = lane >> 2, t = lane & 3;
    int m0 = blockIdx.y * 128;
    int n0 = blockIdx.x * 128;

    int lr = tid >> 1;
    int h = tid & 1;
    const uint4* Ag = A4 + (size_t)(m0 + lr) * 128 + 2 * h;
    const uint4* Bg = B4 + (size_t)(n0 + lr) * 128 + 2 * h;

    float acc[4][4][4];
    #pragma unroll
    for (int i = 0; i < 4; i++)
        #pragma unroll
        for (int j = 0; j < 4; j++)
            #pragma unroll
            for (int k = 0; k < 4; k++) acc[i][j][k] = 0.f;

    // prologue: stages 0,1 (chunks 0..3)
    #pragma unroll
    for (int p = 0; p < 2; p++) {
        #pragma unroll
        for (int c = 0; c < 2; c++) {
            int kc = p * 2 + c;
            uint32_t da = smem_u32(&SB2(p, 0, c, lr, 2 * h));
            uint32_t db = smem_u32(&SB2(p, 1, c, lr, 2 * h));
            cp16(da, Ag + kc * 4);      cp16(da + 16, Ag + kc * 4 + 1);
            cp16(db, Bg + kc * 4);      cp16(db + 16, Bg + kc * 4 + 1);
        }
        cp_commit();
    }

    int arow = warpM * 64 + g;
    int bn = warpN * 32 + g;

    for (int st = 0; st < NSTG; st++) {
        if (st >= NSTG - 2) cp_wait0(); else cp_wait1();
        __syncthreads();

        if (st + 2 < NSTG) {
            int ps = (st + 2) % 3;
            #pragma unroll
            for (int c = 0; c < 2; c++) {
                int kc = (st + 2) * 2 + c;
                uint32_t da = smem_u32(&SB2(ps, 0, c, lr, 2 * h));
                uint32_t db = smem_u32(&SB2(ps, 1, c, lr, 2 * h));
                cp16(da, Ag + kc * 4);  cp16(da + 16, Ag + kc * 4 + 1);
                cp16(db, Bg + kc * 4);  cp16(db + 16, Bg + kc * 4 + 1);
            }
            cp_commit();
        }

        int s = st % 3;
        #pragma unroll
        for (int c = 0; c < 2; c++) {
            uint32_t a1[4][4], a2[4][4], b1[4][2], b2[4][2];
            #pragma unroll
            for (int mt = 0; mt < 4; mt++) {
                uint4 va  = SB2(s, 0, c, arow + mt * 16, t);
                uint4 va8 = SB2(s, 0, c, arow + mt * 16 + 8, t);
                a1[mt][0] = va.x; a1[mt][1] = va8.x; a1[mt][2] = va.y; a1[mt][3] = va8.y;
                a2[mt][0] = va.z; a2[mt][1] = va8.z; a2[mt][2] = va.w; a2[mt][3] = va8.w;
            }
            #pragma unroll
            for (int nt = 0; nt < 4; nt++) {
                uint4 vb = SB2(s, 1, c, bn + nt * 8, t);
                b1[nt][0] = vb.x; b1[nt][1] = vb.y;
                b2[nt][0] = vb.z; b2[nt][1] = vb.w;
            }
            #pragma unroll
            for (int mt = 0; mt < 4; mt++)
                #pragma unroll
                for (int nt = 0; nt < 4; nt++) {
                    mma_bf16(acc[mt][nt], a1[mt], b1[nt]);
                    mma_bf16(acc[mt][nt], a1[mt], b2[nt]);
                    mma_bf16(acc[mt][nt], a2[mt], b1[nt]);
                }
        }
    }

    #pragma unroll
    for (int mt = 0; mt < 4; mt++) {
        int row0 = m0 + warpM * 64 + mt * 16 + g;
        #pragma unroll
        for (int half = 0; half < 2; half++) {
            int row = row0 + half * 8;
            if (row >= M) continue;
            #pragma unroll
            for (int nt = 0; nt < 4; nt++) {
                int col = n0 + warpN * 32 + nt * 8 + t * 2;
                float v0 = acc[mt][nt][half * 2 + 0];
                float v1 = acc[mt][nt][half * 2 + 1];
                if (MODE == 3) {
                    float2 bb = *(const float2*)&bias[col];
                    float2 rr = *(const float2*)&R[(size_t)row * FDIM + col];
                    v0 = fmaxf(v0 + bb.x, 0.f) + rr.x;
                    v1 = fmaxf(v1 + bb.y, 0.f) + rr.y;
                }
                *(float2*)&C[(size_t)row * FDIM + col] = make_float2(v0, v1);
            }
        }
    }
}

// ---------------- layernorm ----------------
__global__ void k_ln(float* __restrict__ io, const float* __restrict__ gamma,
                     const float* __restrict__ beta) {
    int r = blockIdx.x;
    int t = threadIdx.x;
    float4* row = ((float4*)io) + (size_t)r * F4;
    float4 v = row[t];
    float s = v.x + v.y + v.z + v.w;
    float q = v.x * v.x + v.y * v.y + v.z * v.z + v.w * v.w;
    #pragma unroll
    for (int off = 16; off; off >>= 1) {
        s += __shfl_xor_sync(0xffffffffu, s, off);
        q += __shfl_xor_sync(0xffffffffu, q, off);
    }
    __shared__ float ss[4], sq[4];
    if ((t & 31) == 0) { ss[t >> 5] = s; sq[t >> 5] = q; }
    __syncthreads();
    s = ss[0] + ss[1] + ss[2] + ss[3];
    q = sq[0] + sq[1] + sq[2] + sq[3];
    float mu = s * (1.f / FDIM);
    float var = q * (1.f / FDIM) - mu * mu;
    float inv = rsqrtf(var + LNEPS);
    float4 g = ((const float4*)gamma)[t];
    float4 bb = ((const float4*)beta)[t];
    v.x = (v.x - mu) * inv * g.x + bb.x;
    v.y = (v.y - mu) * inv * g.y + bb.y;
    v.z = (v.z - mu) * inv * g.z + bb.z;
    v.w = (v.w - mu) * inv * g.w + bb.w;
    row[t] = v;
}

// ---------------- host-side side-stream (created once, host resources only) --
static cudaStream_t g_s2 = nullptr;
static cudaEvent_t  g_ev1 = nullptr, g_ev2 = nullptr;
static int          g_res_init = 0;

// ---------------- launch ----------------
extern "C" void kernel_launch(void* const* d_in, const int* in_sizes, int n_in,
                              void* d_out, int out_size) {
    const float* x     = (const float*)d_in[0];
    const int*   ei    = (const int*)d_in[1];
    const float* ts    = (const float*)d_in[2];
    const float* Wt    = (const float*)d_in[3];
    const float* bt    = (const float*)d_in[4];
    const float* Wr    = (const float*)d_in[5];
    const float* gamma = (const float*)d_in[6];
    const float* beta  = (const float*)d_in[7];
    const void*  gt    = d_in[8];

    int n = in_sizes[0] / FDIM;
    int e = in_sizes[1] / 2;

    float *h0, *h1, *xr;
    uint2 *hfA, *hfB;
    uint4 *ca, *cx, *cwt, *cwr;
    cudaGetSymbolAddress((void**)&h0, g_h0);
    cudaGetSymbolAddress((void**)&h1, g_h1);
    cudaGetSymbolAddress((void**)&xr, g_xr);
    cudaGetSymbolAddress((void**)&hfA, g_hfA);
    cudaGetSymbolAddress((void**)&hfB, g_hfB);
    cudaGetSymbolAddress((void**)&ca, g_ca);
    cudaGetSymbolAddress((void**)&cx, g_cx);
    cudaGetSymbolAddress((void**)&cwt, g_cwt);
    cudaGetSymbolAddress((void**)&cwr, g_cwr);

    cudaFuncSetAttribute(k_gemm_mma<2>, cudaFuncAttributeMaxDynamicSharedMemorySize, SMEMB);
    cudaFuncSetAttribute(k_gemm_mma<3>, cudaFuncAttributeMaxDynamicSharedMemorySize, SMEMB);

    // one-time host resources (first call = uncaptured correctness run)
    if (!g_res_init) {
        g_res_init = 1;
        if (cudaStreamCreateWithFlags(&g_s2, cudaStreamNonBlocking) != cudaSuccess)
            g_s2 = nullptr;
        if (g_s2) {
            if (cudaEventCreateWithFlags(&g_ev1, cudaEventDisableTiming) != cudaSuccess ||
                cudaEventCreateWithFlags(&g_ev2, cudaEventDisableTiming) != cudaSuccess)
                g_s2 = nullptr;
        }
    }
    bool fork = (g_s2 != nullptr);

    const int tb = 256;
    dim3 gg(FDIM / 128, (n + 127) / 128);   // (4, 157)
    int gb = (n + 7) / 8;

    k_cvtw3<<<(2 * 512 * 64 + n * 64 + tb - 1) / tb, tb>>>(Wt, Wr, x, cwt, cwr, cx, n * 64);
    if (fork) {
        cudaEventRecord(g_ev1, 0);
        cudaStreamWaitEvent(g_s2, g_ev1, 0);
    }
    k_prep<<<(n + tb - 1) / tb, tb>>>(ts, e, n, gt);
    k_edge_deg<<<(e + tb - 1) / tb, tb>>>(ei, ts, e);

    // xr = x@Wr^T on the side stream, overlapped with prep + diffusion
    k_gemm_mma<2><<<gg, 256, SMEMB, fork ? g_s2 : 0>>>(cx, cwr, nullptr, nullptr, xr, n);
    if (fork) cudaEventRecord(g_ev2, g_s2);

    k_scan<<<1, 1024>>>(n, gt);
    k_scatter<<<(e + tb - 1) / tb, tb>>>(ei, ts, e);

    // 5 Euler diffusion steps; step 1 gathers fp32 x, step 5 emits split-bf16
    k_diff<0, 0><<<gb, 256>>>((const float4*)x,  nullptr, (float4*)h1, hfB, nullptr, n);
    k_diff<1, 0><<<gb, 256>>>((const float4*)h1, hfB, (float4*)h0, hfA, nullptr, n);
    k_diff<1, 0><<<gb, 256>>>((const float4*)h0, hfA, (float4*)h1, hfB, nullptr, n);
    k_diff<1, 0><<<gb, 256>>>((const float4*)h1, hfB, (float4*)h0, hfA, nullptr, n);
    k_diff<1, 1><<<gb, 256>>>((const float4*)h0, hfA, nullptr, nullptr, ca, n);

    if (fork) cudaStreamWaitEvent(0, g_ev2, 0);   // join: gemm<3> reads xr

    float* out = (float*)d_out;
    k_gemm_mma<3><<<gg, 256, SMEMB>>>(ca, cwt, bt, xr, out, n);  // out = relu(h@Wt^T+b)+xr
    k_ln<<<n, 128>>>(out, gamma, beta);
}